// round 1
// baseline (speedup 1.0000x reference)
#include <cuda_runtime.h>
#include <cstdint>

#define B_   2048
#define D_   4096
#define E_   512
#define NN_  8192
#define BN_EPS  1e-5f
#define COS_EPSF 1e-8f

// ---------------- scratch (__device__ globals; no allocations allowed) ----------------
__device__ float g_psum[32][D_];
__device__ float g_psq [32][D_];
__device__ float g_scale[D_];
__device__ float g_shift[D_];
__device__ float g_vfn[B_ * D_];      // 33.5 MB
__device__ float g_pe [B_];
__device__ float g_emb[B_ * E_];      // 4 MB
__device__ float g_nwn[NN_ * E_];     // 16 MB

// ---------------- helpers ----------------
__device__ __forceinline__ uint32_t cvt_tf32(float x) {
    uint32_t r;
    asm("cvt.rna.tf32.f32 %0, %1;" : "=r"(r) : "f"(x));
    return r;
}

__device__ __forceinline__ void cp16(uint32_t dst, const void* src) {
    asm volatile("cp.async.cg.shared.global [%0], [%1], 16;" :: "r"(dst), "l"(src));
}

// ---------------- BN column stats (deterministic two-pass) ----------------
__global__ void k_stats_partial(const float* __restrict__ vf) {
    const int c = blockIdx.x * 256 + threadIdx.x;   // column
    const int chunk = blockIdx.y;                   // 0..31
    const int r0 = chunk * 64;
    float s = 0.f, q = 0.f;
    #pragma unroll 4
    for (int r = 0; r < 64; r++) {
        float v = vf[(size_t)(r0 + r) * D_ + c];
        s += v;
        q += v * v;
    }
    g_psum[chunk][c] = s;
    g_psq [chunk][c] = q;
}

__global__ void k_stats_final(const float* __restrict__ gamma,
                              const float* __restrict__ beta) {
    const int c = blockIdx.x * 256 + threadIdx.x;
    float s = 0.f, q = 0.f;
    #pragma unroll
    for (int i = 0; i < 32; i++) { s += g_psum[i][c]; q += g_psq[i][c]; }
    const float mean = s * (1.0f / B_);
    const float var  = q * (1.0f / B_) - mean * mean;
    const float sc   = gamma[c] * rsqrtf(var + BN_EPS);
    g_scale[c] = sc;
    g_shift[c] = beta[c] - mean * sc;
}

// ---------------- fused BN apply + p_e (row cosine) ----------------
__global__ void k_bn_pe(const float* __restrict__ vf, const float* __restrict__ p) {
    const int row = blockIdx.x;
    const int t = threadIdx.x;
    const float4* v4  = (const float4*)(vf + (size_t)row * D_);
    const float4* p4  = (const float4*)(p  + (size_t)row * D_);
    const float4* sc4 = (const float4*)g_scale;
    const float4* sh4 = (const float4*)g_shift;
    float4* o4 = (float4*)(g_vfn + (size_t)row * D_);

    float dot = 0.f, nv = 0.f, np = 0.f;
    for (int i = t; i < D_ / 4; i += 256) {
        float4 v = v4[i], pp = p4[i], sc = sc4[i], sh = sh4[i];
        float4 x;
        x.x = v.x * sc.x + sh.x;
        x.y = v.y * sc.y + sh.y;
        x.z = v.z * sc.z + sh.z;
        x.w = v.w * sc.w + sh.w;
        o4[i] = x;
        dot += x.x * pp.x + x.y * pp.y + x.z * pp.z + x.w * pp.w;
        nv  += x.x * x.x + x.y * x.y + x.z * x.z + x.w * x.w;
        np  += pp.x * pp.x + pp.y * pp.y + pp.z * pp.z + pp.w * pp.w;
    }
    #pragma unroll
    for (int o = 16; o; o >>= 1) {
        dot += __shfl_down_sync(0xffffffffu, dot, o);
        nv  += __shfl_down_sync(0xffffffffu, nv,  o);
        np  += __shfl_down_sync(0xffffffffu, np,  o);
    }
    __shared__ float sd[8], sn[8], sp[8];
    const int lane = t & 31, w = t >> 5;
    if (lane == 0) { sd[w] = dot; sn[w] = nv; sp[w] = np; }
    __syncthreads();
    if (t == 0) {
        float Dv = 0.f, NV = 0.f, NP = 0.f;
        #pragma unroll
        for (int i = 0; i < 8; i++) { Dv += sd[i]; NV += sn[i]; NP += sp[i]; }
        g_pe[row] = Dv / (fmaxf(sqrtf(NV), COS_EPSF) * fmaxf(sqrtf(NP), COS_EPSF));
    }
}

// ---------------- row-normalize a [rows, 512] f32 matrix (128 threads/row) ------------
__global__ void k_rownorm(const float4* __restrict__ src, float4* __restrict__ dst) {
    const int row = blockIdx.x;
    const int t = threadIdx.x;     // 0..127, one float4 each (512 floats/row)
    float4 v = src[(size_t)row * 128 + t];
    float s = v.x * v.x + v.y * v.y + v.z * v.z + v.w * v.w;
    #pragma unroll
    for (int o = 16; o; o >>= 1) s += __shfl_down_sync(0xffffffffu, s, o);
    __shared__ float ss[4];
    if ((t & 31) == 0) ss[t >> 5] = s;
    __syncthreads();
    const float tot = ss[0] + ss[1] + ss[2] + ss[3];
    const float inv = 1.0f / fmaxf(sqrtf(tot), COS_EPSF);
    v.x *= inv; v.y *= inv; v.z *= inv; v.w *= inv;
    dst[(size_t)row * 128 + t] = v;
}

// ---------------- TF32 mma.sync GEMM  C[M,N] = A[M,K] * B[N,K]^T ----------------
// EPI 0: out = relu(C + bias)  (GEMM1 -> g_emb)
// EPI 1: out[r*N+c] = C; out[off2 + r*N+c] = pe[r]  (GEMM2 -> d_out)
template<int BM, int EPI>
__global__ void __launch_bounds__(256)
k_gemm(const float* __restrict__ A, const float* __restrict__ Bm,
       const float* __restrict__ bias, float* __restrict__ out,
       const float* __restrict__ pe, int M, int N, int K, size_t off2)
{
    constexpr int BK = 32, BN = 128, LDSS = 40;  // pad 32->40 floats
    constexpr int WM = BM / 2, MT = WM / 16, NT = 4;
    extern __shared__ float smem[];
    float* As = smem;                      // [2][BM][LDSS]
    float* Bs = smem + 2 * BM * LDSS;      // [2][BN][LDSS]
    const int t = threadIdx.x, lane = t & 31, warp = t >> 5;
    const int wm = warp >> 2, wn = warp & 3;
    const int m0 = blockIdx.y * BM, n0 = blockIdx.x * BN;
    const uint32_t sAu = (uint32_t)__cvta_generic_to_shared(As);
    const uint32_t sBu = (uint32_t)__cvta_generic_to_shared(Bs);

    float acc[MT][NT][4];
    #pragma unroll
    for (int i = 0; i < MT; i++)
        #pragma unroll
        for (int j = 0; j < NT; j++)
            #pragma unroll
            for (int q = 0; q < 4; q++) acc[i][j][q] = 0.f;

    const int KT = K / BK;

    auto load_tile = [&](int buf, int kt) {
        const int k0 = kt * BK;
        #pragma unroll
        for (int f = t; f < BM * 8; f += 256) {
            int r = f >> 3, c = (f & 7) * 4;
            cp16(sAu + 4u * (uint32_t)((buf * BM + r) * LDSS + c),
                 A + (size_t)(m0 + r) * K + k0 + c);
        }
        #pragma unroll
        for (int f = t; f < BN * 8; f += 256) {
            int r = f >> 3, c = (f & 7) * 4;
            cp16(sBu + 4u * (uint32_t)((buf * BN + r) * LDSS + c),
                 Bm + (size_t)(n0 + r) * K + k0 + c);
        }
        asm volatile("cp.async.commit_group;" ::: "memory");
    };

    load_tile(0, 0);
    int buf = 0;
    for (int kt = 0; kt < KT; kt++) {
        asm volatile("cp.async.wait_group 0;" ::: "memory");
        __syncthreads();
        if (kt + 1 < KT) load_tile(buf ^ 1, kt + 1);

        const float* At = As + buf * BM * LDSS;
        const float* Bt = Bs + buf * BN * LDSS;
        #pragma unroll
        for (int ks = 0; ks < 4; ks++) {
            const int kk = ks * 8 + (lane & 3);
            uint32_t af[MT][4];
            #pragma unroll
            for (int mt = 0; mt < MT; mt++) {
                const int rb = wm * WM + mt * 16 + (lane >> 2);
                af[mt][0] = cvt_tf32(At[rb * LDSS + kk]);
                af[mt][1] = cvt_tf32(At[(rb + 8) * LDSS + kk]);
                af[mt][2] = cvt_tf32(At[rb * LDSS + kk + 4]);
                af[mt][3] = cvt_tf32(At[(rb + 8) * LDSS + kk + 4]);
            }
            uint32_t bf[NT][2];
            #pragma unroll
            for (int nt = 0; nt < NT; nt++) {
                const int cb = wn * 32 + nt * 8 + (lane >> 2);
                bf[nt][0] = cvt_tf32(Bt[cb * LDSS + kk]);
                bf[nt][1] = cvt_tf32(Bt[cb * LDSS + kk + 4]);
            }
            #pragma unroll
            for (int mt = 0; mt < MT; mt++)
                #pragma unroll
                for (int nt = 0; nt < NT; nt++)
                    asm volatile(
                        "mma.sync.aligned.m16n8k8.row.col.f32.tf32.tf32.f32 "
                        "{%0,%1,%2,%3}, {%4,%5,%6,%7}, {%8,%9}, {%0,%1,%2,%3};"
                        : "+f"(acc[mt][nt][0]), "+f"(acc[mt][nt][1]),
                          "+f"(acc[mt][nt][2]), "+f"(acc[mt][nt][3])
                        : "r"(af[mt][0]), "r"(af[mt][1]), "r"(af[mt][2]), "r"(af[mt][3]),
                          "r"(bf[nt][0]), "r"(bf[nt][1]));
        }
        buf ^= 1;
    }

    // epilogue
    #pragma unroll
    for (int mt = 0; mt < MT; mt++) {
        const int row = m0 + wm * WM + mt * 16 + (lane >> 2);
        float pv0 = 0.f, pv1 = 0.f;
        if (EPI == 1) { pv0 = pe[row]; pv1 = pe[row + 8]; }
        #pragma unroll
        for (int nt = 0; nt < NT; nt++) {
            const int col = n0 + wn * 32 + nt * 8 + 2 * (lane & 3);
            if (EPI == 0) {
                const float b0 = bias[col], b1 = bias[col + 1];
                out[(size_t)row * N + col]         = fmaxf(acc[mt][nt][0] + b0, 0.f);
                out[(size_t)row * N + col + 1]     = fmaxf(acc[mt][nt][1] + b1, 0.f);
                out[(size_t)(row + 8) * N + col]     = fmaxf(acc[mt][nt][2] + b0, 0.f);
                out[(size_t)(row + 8) * N + col + 1] = fmaxf(acc[mt][nt][3] + b1, 0.f);
            } else {
                *reinterpret_cast<float2*>(out + (size_t)row * N + col) =
                    make_float2(acc[mt][nt][0], acc[mt][nt][1]);
                *reinterpret_cast<float2*>(out + (size_t)(row + 8) * N + col) =
                    make_float2(acc[mt][nt][2], acc[mt][nt][3]);
                *reinterpret_cast<float2*>(out + off2 + (size_t)row * N + col) =
                    make_float2(pv0, pv0);
                *reinterpret_cast<float2*>(out + off2 + (size_t)(row + 8) * N + col) =
                    make_float2(pv1, pv1);
            }
        }
    }
}

// ---------------- launch ----------------
extern "C" void kernel_launch(void* const* d_in, const int* in_sizes, int n_in,
                              void* d_out, int out_size)
{
    const float* vf    = (const float*)d_in[0];
    const float* pwfs  = (const float*)d_in[1];
    const float* nwfs  = (const float*)d_in[2];
    const float* gamma = (const float*)d_in[3];
    const float* beta  = (const float*)d_in[4];
    const float* W     = (const float*)d_in[5];
    const float* bias  = (const float*)d_in[6];
    float* out = (float*)d_out;

    float *vfn_p, *emb_p, *nwn_p, *pe_p;
    cudaGetSymbolAddress((void**)&vfn_p, g_vfn);
    cudaGetSymbolAddress((void**)&emb_p, g_emb);
    cudaGetSymbolAddress((void**)&nwn_p, g_nwn);
    cudaGetSymbolAddress((void**)&pe_p,  g_pe);

    // 1-2: BN stats
    k_stats_partial<<<dim3(D_ / 256, 32), 256>>>(vf);
    k_stats_final<<<D_ / 256, 256>>>(gamma, beta);
    // 3: BN apply + p_e
    k_bn_pe<<<B_, 256>>>(vf, pwfs);
    // 4: normalize n_wfs rows
    k_rownorm<<<NN_, 128>>>((const float4*)nwfs, (float4*)nwn_p);

    // 5: GEMM1 emb = relu(vfn @ W^T + b)   [2048,512,K=4096], BM=64 -> 128 blocks
    const int sm1 = (2 * 64 * 40 + 2 * 128 * 40) * 4;
    cudaFuncSetAttribute(k_gemm<64, 0>, cudaFuncAttributeMaxDynamicSharedMemorySize, sm1);
    k_gemm<64, 0><<<dim3(E_ / 128, B_ / 64), 256, sm1>>>(
        vfn_p, W, bias, emb_p, nullptr, B_, E_, D_, 0);

    // 6: normalize emb rows (in place)
    k_rownorm<<<B_, 128>>>((const float4*)emb_p, (float4*)emb_p);

    // 7: GEMM2 n_e = embn @ nwn^T, fused p_e_stack broadcast  [2048,8192,K=512]
    const int sm2 = (2 * 128 * 40 + 2 * 128 * 40) * 4;
    cudaFuncSetAttribute(k_gemm<128, 1>, cudaFuncAttributeMaxDynamicSharedMemorySize, sm2);
    const size_t off2 = (size_t)out_size / 2;
    k_gemm<128, 1><<<dim3(NN_ / 128, B_ / 128), 256, sm2>>>(
        emb_p, nwn_p, nullptr, out, pe_p, B_, NN_, E_, off2);
}

// round 3
// speedup vs baseline: 1.4577x; 1.4577x over previous
#include <cuda_runtime.h>
#include <cstdint>

#define B_   2048
#define D_   4096
#define E_   512
#define NN_  8192
#define BN_EPS  1e-5f
#define COS_EPSF 1e-8f

// ---------------- scratch (__device__ globals; no allocations allowed) ----------------
__device__ float g_psum[32][D_];
__device__ float g_psq [32][D_];
__device__ float g_scale[D_];
__device__ float g_shift[D_];
__device__ float g_vfn[B_ * D_];        // 33.5 MB (tf32-rounded)
__device__ float g_pe [B_];
__device__ float g_emb[B_ * E_];        // 4 MB (normalized, tf32-rounded)
__device__ float g_nwn[NN_ * E_];       // 16 MB (normalized, tf32-rounded)
__device__ float g_wr [E_ * D_];        // 8 MB (tf32-rounded W)
__device__ float g_part[4][B_ * E_];    // 16 MB split-K partials

// ---------------- helpers ----------------
__device__ __forceinline__ float tf32r(float x) {
    uint32_t u; asm("cvt.rna.tf32.f32 %0, %1;" : "=r"(u) : "f"(x));
    return __uint_as_float(u);
}
__device__ __forceinline__ void cp16(uint32_t dst, const void* src) {
    asm volatile("cp.async.cg.shared.global [%0], [%1], 16;" :: "r"(dst), "l"(src));
}
#define SW128(o) ((o) ^ (((o) >> 3) & 0x70))

#define LDSM4(r0, r1, r2, r3, a) \
    asm volatile("ldmatrix.sync.aligned.m8n8.x4.shared.b16 {%0,%1,%2,%3}, [%4];" \
                 : "=r"(r0), "=r"(r1), "=r"(r2), "=r"(r3) : "r"(a))

#define MMA8(d, av, bv) \
    asm volatile("mma.sync.aligned.m16n8k8.row.col.f32.tf32.tf32.f32 " \
                 "{%0,%1,%2,%3}, {%4,%5,%6,%7}, {%8,%9}, {%0,%1,%2,%3};" \
                 : "+f"((d)[0]), "+f"((d)[1]), "+f"((d)[2]), "+f"((d)[3]) \
                 : "r"((av)[0]), "r"((av)[1]), "r"((av)[2]), "r"((av)[3]), \
                   "r"((bv)[0]), "r"((bv)[1]))

// ---------------- W rounding copy ----------------
__global__ void k_round(const float4* __restrict__ src, float4* __restrict__ dst, int n4) {
    const int i = blockIdx.x * 256 + threadIdx.x;
    if (i < n4) {
        float4 v = src[i];
        v.x = tf32r(v.x); v.y = tf32r(v.y); v.z = tf32r(v.z); v.w = tf32r(v.w);
        dst[i] = v;
    }
}

// ---------------- BN column stats (deterministic two-pass) ----------------
__global__ void k_stats_partial(const float* __restrict__ vf) {
    const int c = blockIdx.x * 256 + threadIdx.x;
    const int chunk = blockIdx.y;
    const int r0 = chunk * 64;
    float s = 0.f, q = 0.f;
    #pragma unroll 4
    for (int r = 0; r < 64; r++) {
        float v = vf[(size_t)(r0 + r) * D_ + c];
        s += v; q += v * v;
    }
    g_psum[chunk][c] = s;
    g_psq [chunk][c] = q;
}

__global__ void k_stats_final(const float* __restrict__ gamma,
                              const float* __restrict__ beta) {
    const int c = blockIdx.x * 256 + threadIdx.x;
    float s = 0.f, q = 0.f;
    #pragma unroll
    for (int i = 0; i < 32; i++) { s += g_psum[i][c]; q += g_psq[i][c]; }
    const float mean = s * (1.0f / B_);
    const float var  = q * (1.0f / B_) - mean * mean;
    const float sc   = gamma[c] * rsqrtf(var + BN_EPS);
    g_scale[c] = sc;
    g_shift[c] = beta[c] - mean * sc;
}

// ---------------- fused BN apply + p_e (row cosine); stores tf32-rounded vfn ---------
__global__ void k_bn_pe(const float* __restrict__ vf, const float* __restrict__ p) {
    const int row = blockIdx.x;
    const int t = threadIdx.x;
    const float4* v4  = (const float4*)(vf + (size_t)row * D_);
    const float4* p4  = (const float4*)(p  + (size_t)row * D_);
    const float4* sc4 = (const float4*)g_scale;
    const float4* sh4 = (const float4*)g_shift;
    float4* o4 = (float4*)(g_vfn + (size_t)row * D_);

    float dot = 0.f, nv = 0.f, np = 0.f;
    for (int i = t; i < D_ / 4; i += 256) {
        float4 v = v4[i], pp = p4[i], sc = sc4[i], sh = sh4[i];
        float4 x;
        x.x = v.x * sc.x + sh.x;
        x.y = v.y * sc.y + sh.y;
        x.z = v.z * sc.z + sh.z;
        x.w = v.w * sc.w + sh.w;
        float4 xr;
        xr.x = tf32r(x.x); xr.y = tf32r(x.y); xr.z = tf32r(x.z); xr.w = tf32r(x.w);
        o4[i] = xr;
        dot += x.x * pp.x + x.y * pp.y + x.z * pp.z + x.w * pp.w;
        nv  += x.x * x.x + x.y * x.y + x.z * x.z + x.w * x.w;
        np  += pp.x * pp.x + pp.y * pp.y + pp.z * pp.z + pp.w * pp.w;
    }
    #pragma unroll
    for (int o = 16; o; o >>= 1) {
        dot += __shfl_down_sync(0xffffffffu, dot, o);
        nv  += __shfl_down_sync(0xffffffffu, nv,  o);
        np  += __shfl_down_sync(0xffffffffu, np,  o);
    }
    __shared__ float sd[8], sn[8], sp[8];
    const int lane = t & 31, w = t >> 5;
    if (lane == 0) { sd[w] = dot; sn[w] = nv; sp[w] = np; }
    __syncthreads();
    if (t == 0) {
        float Dv = 0.f, NV = 0.f, NP = 0.f;
        #pragma unroll
        for (int i = 0; i < 8; i++) { Dv += sd[i]; NV += sn[i]; NP += sp[i]; }
        g_pe[row] = Dv / (fmaxf(sqrtf(NV), COS_EPSF) * fmaxf(sqrtf(NP), COS_EPSF));
    }
}

// ---------------- row-normalize [rows, 512] + tf32-round ----------------
__global__ void k_rownorm(const float4* __restrict__ src, float4* __restrict__ dst) {
    const int row = blockIdx.x;
    const int t = threadIdx.x;     // 0..127
    float4 v = src[(size_t)row * 128 + t];
    float s = v.x * v.x + v.y * v.y + v.z * v.z + v.w * v.w;
    #pragma unroll
    for (int o = 16; o; o >>= 1) s += __shfl_down_sync(0xffffffffu, s, o);
    __shared__ float ss[4];
    if ((t & 31) == 0) ss[t >> 5] = s;
    __syncthreads();
    const float tot = ss[0] + ss[1] + ss[2] + ss[3];
    const float inv = 1.0f / fmaxf(sqrtf(tot), COS_EPSF);
    v.x = tf32r(v.x * inv); v.y = tf32r(v.y * inv);
    v.z = tf32r(v.z * inv); v.w = tf32r(v.w * inv);
    dst[(size_t)row * 128 + t] = v;
}

// ---------------- split-K reduce + bias + relu + rownorm + round -> g_emb -----------
__global__ void k_fuse_emb(const float* __restrict__ bias) {
    const int row = blockIdx.x;     // 2048
    const int t = threadIdx.x;      // 128
    float4 s = make_float4(0.f, 0.f, 0.f, 0.f);
    #pragma unroll
    for (int p = 0; p < 4; p++) {
        const float4 v = *(const float4*)(&g_part[p][(size_t)row * E_ + t * 4]);
        s.x += v.x; s.y += v.y; s.z += v.z; s.w += v.w;
    }
    const float4 bq = ((const float4*)bias)[t];
    s.x = fmaxf(s.x + bq.x, 0.f);
    s.y = fmaxf(s.y + bq.y, 0.f);
    s.z = fmaxf(s.z + bq.z, 0.f);
    s.w = fmaxf(s.w + bq.w, 0.f);
    float nrm = s.x * s.x + s.y * s.y + s.z * s.z + s.w * s.w;
    #pragma unroll
    for (int o = 16; o; o >>= 1) nrm += __shfl_down_sync(0xffffffffu, nrm, o);
    __shared__ float ss[4];
    if ((t & 31) == 0) ss[t >> 5] = nrm;
    __syncthreads();
    const float tot = ss[0] + ss[1] + ss[2] + ss[3];
    const float inv = 1.0f / fmaxf(sqrtf(tot), COS_EPSF);
    float4 o;
    o.x = tf32r(s.x * inv); o.y = tf32r(s.y * inv);
    o.z = tf32r(s.z * inv); o.w = tf32r(s.w * inv);
    *(float4*)(&g_emb[(size_t)row * E_ + t * 4]) = o;
}

// ---------------- tf32 mma.sync GEMM  C[M,N] = A[M,K_chunk] @ B[N,K_chunk]^T --------
// EPI 0: split-K partial store (out += z*M*N, k0 = z*kcnt)
// EPI 1: out[r*N+c] = C; out[off2 + r*N+c] = pe[r]
template<int BN, int EPI>
__global__ void __launch_bounds__(BN == 256 ? 512 : 256, BN == 256 ? 1 : 2)
k_mma(const float* __restrict__ A, const float* __restrict__ Bm,
      float* __restrict__ out, const float* __restrict__ pe,
      int M, int N, int K, int kcnt, size_t off2)
{
    constexpr int BM = 128, BK = 32, STAGES = 3;
    constexpr int T = (BN == 256) ? 512 : 256;
    constexpr int NWN = BN / 32;                // warps along N
    constexpr int ABYTES = BM * BK * 4;         // 16 KB / stage
    constexpr int BBYTES = BN * BK * 4;

    extern __shared__ char smem[];
    const uint32_t smA = (uint32_t)__cvta_generic_to_shared(smem);
    const uint32_t smB = smA + STAGES * ABYTES;

    const int t = threadIdx.x, lane = t & 31, warp = t >> 5;
    const int wm = warp / NWN, wn = warp % NWN;
    const int m0 = blockIdx.y * BM, n0 = blockIdx.x * BN;
    int k0 = 0;
    if (EPI == 0) { k0 = blockIdx.z * kcnt; out += (size_t)blockIdx.z * M * N; }

    // per-thread ldmatrix address components
    const int idx = lane & 7, g = lane >> 3;
    const uint32_t xorv = (uint32_t)idx * 16u;
    uint32_t aoff[4], boff[2], acx[4], bcx[4];
    #pragma unroll
    for (int mt = 0; mt < 4; mt++)
        aoff[mt] = (uint32_t)((wm * 64 + mt * 16 + (g & 1) * 8 + idx) * 128);
    #pragma unroll
    for (int p = 0; p < 2; p++)
        boff[p] = (uint32_t)((wn * 32 + (p * 2 + (g >> 1)) * 8 + idx) * 128);
    #pragma unroll
    for (int ks = 0; ks < 4; ks++) {
        acx[ks] = ((uint32_t)(ks * 32) | (uint32_t)((g >> 1) * 16)) ^ xorv;
        bcx[ks] = ((uint32_t)(ks * 32) | (uint32_t)((g & 1) * 16)) ^ xorv;
    }

    float acc[4][4][4];
    #pragma unroll
    for (int i = 0; i < 4; i++)
        #pragma unroll
        for (int j = 0; j < 4; j++)
            #pragma unroll
            for (int q = 0; q < 4; q++) acc[i][j][q] = 0.f;

    auto load_tile = [&](int stage, int kt) {
        const int kk = k0 + kt * BK;
        #pragma unroll
        for (int f = t; f < BM * 8; f += T) {
            const int r = f >> 3, c = f & 7;
            cp16(smA + (uint32_t)stage * ABYTES + SW128((uint32_t)(r * 128 + c * 16)),
                 A + (size_t)(m0 + r) * K + kk + c * 4);
        }
        #pragma unroll
        for (int f = t; f < BN * 8; f += T) {
            const int r = f >> 3, c = f & 7;
            cp16(smB + (uint32_t)stage * BBYTES + SW128((uint32_t)(r * 128 + c * 16)),
                 Bm + (size_t)(n0 + r) * K + kk + c * 4);
        }
        asm volatile("cp.async.commit_group;" ::: "memory");
    };

    const int KT = kcnt / BK;
    #pragma unroll
    for (int s = 0; s < STAGES; s++) load_tile(s, s);

    for (int kt = 0; kt < KT; kt++) {
        const int st = kt % STAGES;
        asm volatile("cp.async.wait_group %0;" :: "n"(STAGES - 1));
        __syncthreads();
        const uint32_t aB = smA + (uint32_t)st * ABYTES;
        const uint32_t bB = smB + (uint32_t)st * BBYTES;
        #pragma unroll
        for (int ks = 0; ks < 4; ks++) {
            uint32_t a[4][4], b[4][2];
            #pragma unroll
            for (int mt = 0; mt < 4; mt++)
                LDSM4(a[mt][0], a[mt][1], a[mt][2], a[mt][3],
                      aB + aoff[mt] + acx[ks]);
            #pragma unroll
            for (int p = 0; p < 2; p++)
                LDSM4(b[2 * p][0], b[2 * p][1], b[2 * p + 1][0], b[2 * p + 1][1],
                      bB + boff[p] + bcx[ks]);
            #pragma unroll
            for (int mt = 0; mt < 4; mt++)
                #pragma unroll
                for (int nt = 0; nt < 4; nt++)
                    MMA8(acc[mt][nt], a[mt], b[nt]);
        }
        __syncthreads();
        if (kt + STAGES < KT) load_tile(st, kt + STAGES);
        else asm volatile("cp.async.commit_group;" ::: "memory");
    }

    // epilogue
    #pragma unroll
    for (int mt = 0; mt < 4; mt++) {
        const int r = m0 + wm * 64 + mt * 16 + (lane >> 2);
        float pv0 = 0.f, pv1 = 0.f;
        if (EPI == 1) { pv0 = pe[r]; pv1 = pe[r + 8]; }
        #pragma unroll
        for (int nt = 0; nt < 4; nt++) {
            const int c = n0 + wn * 32 + nt * 8 + 2 * (lane & 3);
            *(float2*)(out + (size_t)r * N + c) =
                make_float2(acc[mt][nt][0], acc[mt][nt][1]);
            *(float2*)(out + (size_t)(r + 8) * N + c) =
                make_float2(acc[mt][nt][2], acc[mt][nt][3]);
            if (EPI == 1) {
                *(float2*)(out + off2 + (size_t)r * N + c) = make_float2(pv0, pv0);
                *(float2*)(out + off2 + (size_t)(r + 8) * N + c) = make_float2(pv1, pv1);
            }
        }
    }
}

// ---------------- launch ----------------
extern "C" void kernel_launch(void* const* d_in, const int* in_sizes, int n_in,
                              void* d_out, int out_size)
{
    const float* vf    = (const float*)d_in[0];
    const float* pwfs  = (const float*)d_in[1];
    const float* nwfs  = (const float*)d_in[2];
    const float* gamma = (const float*)d_in[3];
    const float* beta  = (const float*)d_in[4];
    const float* W     = (const float*)d_in[5];
    const float* bias  = (const float*)d_in[6];
    float* out = (float*)d_out;

    float *vfn_p, *emb_p, *nwn_p, *pe_p, *wr_p, *part_p;
    cudaGetSymbolAddress((void**)&vfn_p,  g_vfn);
    cudaGetSymbolAddress((void**)&emb_p,  g_emb);
    cudaGetSymbolAddress((void**)&nwn_p,  g_nwn);
    cudaGetSymbolAddress((void**)&pe_p,   g_pe);
    cudaGetSymbolAddress((void**)&wr_p,   g_wr);
    cudaGetSymbolAddress((void**)&part_p, g_part);

    // 1: round W to tf32
    k_round<<<(E_ * D_ / 4 + 255) / 256, 256>>>((const float4*)W, (float4*)wr_p, E_ * D_ / 4);
    // 2-3: BN stats
    k_stats_partial<<<dim3(D_ / 256, 32), 256>>>(vf);
    k_stats_final<<<D_ / 256, 256>>>(gamma, beta);
    // 4: BN apply (rounded) + p_e
    k_bn_pe<<<B_, 256>>>(vf, pwfs);
    // 5: normalize + round n_wfs
    k_rownorm<<<NN_, 128>>>((const float4*)nwfs, (float4*)nwn_p);

    // 6: GEMM1 split-K=4 partials: part[z] = vfn @ Wr^T (K chunk 1024)
    constexpr int SM1 = 3 * (128 + 128) * 32 * 4;     // 96 KB
    cudaFuncSetAttribute(k_mma<128, 0>, cudaFuncAttributeMaxDynamicSharedMemorySize, SM1);
    k_mma<128, 0><<<dim3(E_ / 128, B_ / 128, 4), 256, SM1>>>(
        vfn_p, wr_p, part_p, nullptr, B_, E_, D_, D_ / 4, 0);

    // 7: reduce partials + bias + relu + rownorm + round -> emb
    k_fuse_emb<<<B_, 128>>>(bias);

    // 8: GEMM2 n_e = embn @ nwn^T + fused p_e broadcast
    constexpr int SM2 = 3 * (128 + 256) * 32 * 4;     // 144 KB
    cudaFuncSetAttribute(k_mma<256, 1>, cudaFuncAttributeMaxDynamicSharedMemorySize, SM2);
    const size_t off2 = (size_t)out_size / 2;
    k_mma<256, 1><<<dim3(NN_ / 256, B_ / 128), 512, SM2>>>(
        emb_p, nwn_p, out, pe_p, B_, NN_, E_, E_, off2);
}

// round 4
// speedup vs baseline: 1.5237x; 1.0453x over previous
#include <cuda_runtime.h>
#include <cstdint>

#define B_   2048
#define D_   4096
#define E_   512
#define NN_  8192
#define BN_EPS  1e-5f
#define COS_EPSF 1e-8f

// ---------------- scratch (__device__ globals; no allocations allowed) ----------------
__device__ float g_psum[32][D_];
__device__ float g_psq [32][D_];
__device__ float g_scale[D_];
__device__ float g_shift[D_];
__device__ float g_vfn[B_ * D_];        // 33.5 MB (tf32-rounded)
__device__ float g_pe [B_];
__device__ float g_emb[B_ * E_];        // 4 MB (normalized, tf32-rounded)
__device__ float g_nwn[NN_ * E_];       // 16 MB (normalized, tf32-rounded)
__device__ float g_wr [E_ * D_];        // 8 MB (tf32-rounded W)
__device__ float g_part[4][B_ * E_];    // 16 MB split-K partials

// ---------------- helpers ----------------
__device__ __forceinline__ float tf32r(float x) {
    uint32_t u; asm("cvt.rna.tf32.f32 %0, %1;" : "=r"(u) : "f"(x));
    return __uint_as_float(u);
}
__device__ __forceinline__ void cp16(uint32_t dst, const void* src) {
    asm volatile("cp.async.cg.shared.global [%0], [%1], 16;" :: "r"(dst), "l"(src));
}
#define SW128(o) ((o) ^ (((o) >> 3) & 0x70))

#define LDSM4(r0, r1, r2, r3, a) \
    asm volatile("ldmatrix.sync.aligned.m8n8.x4.shared.b16 {%0,%1,%2,%3}, [%4];" \
                 : "=r"(r0), "=r"(r1), "=r"(r2), "=r"(r3) : "r"(a))

#define MMA8(d, av, bv) \
    asm volatile("mma.sync.aligned.m16n8k8.row.col.f32.tf32.tf32.f32 " \
                 "{%0,%1,%2,%3}, {%4,%5,%6,%7}, {%8,%9}, {%0,%1,%2,%3};" \
                 : "+f"((d)[0]), "+f"((d)[1]), "+f"((d)[2]), "+f"((d)[3]) \
                 : "r"((av)[0]), "r"((av)[1]), "r"((av)[2]), "r"((av)[3]), \
                   "r"((bv)[0]), "r"((bv)[1]))

// ---------------- merged: W tf32-round (blocks 0..2047) + BN partial stats ----------
__global__ void k_prep(const float4* __restrict__ W, float4* __restrict__ Wr,
                       const float* __restrict__ vf) {
    const int t = threadIdx.x;
    if (blockIdx.x < 2048) {
        const int i = blockIdx.x * 256 + t;      // E*D/4 = 524288 = 2048*256 exactly
        float4 v = W[i];
        v.x = tf32r(v.x); v.y = tf32r(v.y); v.z = tf32r(v.z); v.w = tf32r(v.w);
        Wr[i] = v;
    } else {
        const int bid = blockIdx.x - 2048;       // 0..511
        const int c = (bid & 15) * 256 + t;
        const int chunk = bid >> 4;              // 0..31
        const int r0 = chunk * 64;
        float s = 0.f, q = 0.f;
        #pragma unroll 4
        for (int r = 0; r < 64; r++) {
            float v = vf[(size_t)(r0 + r) * D_ + c];
            s += v; q += v * v;
        }
        g_psum[chunk][c] = s;
        g_psq [chunk][c] = q;
    }
}

__global__ void k_stats_final(const float* __restrict__ gamma,
                              const float* __restrict__ beta) {
    const int c = blockIdx.x * 256 + threadIdx.x;
    float s = 0.f, q = 0.f;
    #pragma unroll
    for (int i = 0; i < 32; i++) { s += g_psum[i][c]; q += g_psq[i][c]; }
    const float mean = s * (1.0f / B_);
    const float var  = q * (1.0f / B_) - mean * mean;
    const float sc   = gamma[c] * rsqrtf(var + BN_EPS);
    g_scale[c] = sc;
    g_shift[c] = beta[c] - mean * sc;
}

// ---------------- fused BN apply + p_e (row cosine); stores tf32-rounded vfn ---------
__global__ void __launch_bounds__(256) k_bn_pe(const float* __restrict__ vf,
                                               const float* __restrict__ p) {
    const int row = blockIdx.x;
    const int t = threadIdx.x;
    const float4* v4  = (const float4*)(vf + (size_t)row * D_);
    const float4* p4  = (const float4*)(p  + (size_t)row * D_);
    const float4* sc4 = (const float4*)g_scale;
    const float4* sh4 = (const float4*)g_shift;
    float4* o4 = (float4*)(g_vfn + (size_t)row * D_);

    float dot = 0.f, nv = 0.f, np = 0.f;
    #pragma unroll
    for (int u = 0; u < 2; u++) {                 // D/4=1024, 256 thr, 4 iters = 2x2
        const int i0 = t + u * 512;
        const float4 va = __ldcs(&v4[i0]);
        const float4 vb = __ldcs(&v4[i0 + 256]);
        const float4 pa = __ldcs(&p4[i0]);
        const float4 pb = __ldcs(&p4[i0 + 256]);
        const float4 sa = sc4[i0], sb = sc4[i0 + 256];
        const float4 ha = sh4[i0], hb = sh4[i0 + 256];
        float4 xa, xb;
        xa.x = va.x * sa.x + ha.x; xa.y = va.y * sa.y + ha.y;
        xa.z = va.z * sa.z + ha.z; xa.w = va.w * sa.w + ha.w;
        xb.x = vb.x * sb.x + hb.x; xb.y = vb.y * sb.y + hb.y;
        xb.z = vb.z * sb.z + hb.z; xb.w = vb.w * sb.w + hb.w;
        float4 ra, rb;
        ra.x = tf32r(xa.x); ra.y = tf32r(xa.y); ra.z = tf32r(xa.z); ra.w = tf32r(xa.w);
        rb.x = tf32r(xb.x); rb.y = tf32r(xb.y); rb.z = tf32r(xb.z); rb.w = tf32r(xb.w);
        o4[i0] = ra;
        o4[i0 + 256] = rb;
        dot += xa.x * pa.x + xa.y * pa.y + xa.z * pa.z + xa.w * pa.w;
        dot += xb.x * pb.x + xb.y * pb.y + xb.z * pb.z + xb.w * pb.w;
        nv  += xa.x * xa.x + xa.y * xa.y + xa.z * xa.z + xa.w * xa.w;
        nv  += xb.x * xb.x + xb.y * xb.y + xb.z * xb.z + xb.w * xb.w;
        np  += pa.x * pa.x + pa.y * pa.y + pa.z * pa.z + pa.w * pa.w;
        np  += pb.x * pb.x + pb.y * pb.y + pb.z * pb.z + pb.w * pb.w;
    }
    #pragma unroll
    for (int o = 16; o; o >>= 1) {
        dot += __shfl_down_sync(0xffffffffu, dot, o);
        nv  += __shfl_down_sync(0xffffffffu, nv,  o);
        np  += __shfl_down_sync(0xffffffffu, np,  o);
    }
    __shared__ float sd[8], sn[8], sp[8];
    const int lane = t & 31, w = t >> 5;
    if (lane == 0) { sd[w] = dot; sn[w] = nv; sp[w] = np; }
    __syncthreads();
    if (t == 0) {
        float Dv = 0.f, NV = 0.f, NP = 0.f;
        #pragma unroll
        for (int i = 0; i < 8; i++) { Dv += sd[i]; NV += sn[i]; NP += sp[i]; }
        g_pe[row] = Dv / (fmaxf(sqrtf(NV), COS_EPSF) * fmaxf(sqrtf(NP), COS_EPSF));
    }
}

// ---------------- row-normalize [rows, 512] + tf32-round ----------------
__global__ void k_rownorm(const float4* __restrict__ src, float4* __restrict__ dst) {
    const int row = blockIdx.x;
    const int t = threadIdx.x;     // 0..127
    float4 v = src[(size_t)row * 128 + t];
    float s = v.x * v.x + v.y * v.y + v.z * v.z + v.w * v.w;
    #pragma unroll
    for (int o = 16; o; o >>= 1) s += __shfl_down_sync(0xffffffffu, s, o);
    __shared__ float ss[4];
    if ((t & 31) == 0) ss[t >> 5] = s;
    __syncthreads();
    const float tot = ss[0] + ss[1] + ss[2] + ss[3];
    const float inv = 1.0f / fmaxf(sqrtf(tot), COS_EPSF);
    v.x = tf32r(v.x * inv); v.y = tf32r(v.y * inv);
    v.z = tf32r(v.z * inv); v.w = tf32r(v.w * inv);
    dst[(size_t)row * 128 + t] = v;
}

// ---------------- split-K reduce + bias + relu + rownorm + round -> g_emb -----------
__global__ void k_fuse_emb(const float* __restrict__ bias) {
    const int row = blockIdx.x;     // 2048
    const int t = threadIdx.x;      // 128
    float4 s = make_float4(0.f, 0.f, 0.f, 0.f);
    #pragma unroll
    for (int p = 0; p < 4; p++) {
        const float4 v = *(const float4*)(&g_part[p][(size_t)row * E_ + t * 4]);
        s.x += v.x; s.y += v.y; s.z += v.z; s.w += v.w;
    }
    const float4 bq = ((const float4*)bias)[t];
    s.x = fmaxf(s.x + bq.x, 0.f);
    s.y = fmaxf(s.y + bq.y, 0.f);
    s.z = fmaxf(s.z + bq.z, 0.f);
    s.w = fmaxf(s.w + bq.w, 0.f);
    float nrm = s.x * s.x + s.y * s.y + s.z * s.z + s.w * s.w;
    #pragma unroll
    for (int o = 16; o; o >>= 1) nrm += __shfl_down_sync(0xffffffffu, nrm, o);
    __shared__ float ss[4];
    if ((t & 31) == 0) ss[t >> 5] = nrm;
    __syncthreads();
    const float tot = ss[0] + ss[1] + ss[2] + ss[3];
    const float inv = 1.0f / fmaxf(sqrtf(tot), COS_EPSF);
    float4 o;
    o.x = tf32r(s.x * inv); o.y = tf32r(s.y * inv);
    o.z = tf32r(s.z * inv); o.w = tf32r(s.w * inv);
    *(float4*)(&g_emb[(size_t)row * E_ + t * 4]) = o;
}

// ---------------- tf32 mma.sync GEMM  C[M,N] = A[M,K_chunk] @ B[N,K_chunk]^T --------
// Single-sync pipeline: wait(tile kt) -> sync -> load(tile kt+S-1) -> compute(kt)
// EPI 0: split-K partial store (out += z*M*N, k0 = z*kcnt)
// EPI 1: out[r*N+c] = C; out[off2 + r*N+c] = pe[r]
template<int BN, int EPI, int STAGES>
__global__ void __launch_bounds__(BN == 256 ? 512 : 256, BN == 256 ? 1 : 2)
k_mma(const float* __restrict__ A, const float* __restrict__ Bm,
      float* __restrict__ out, const float* __restrict__ pe,
      int M, int N, int K, int kcnt, size_t off2)
{
    constexpr int BM = 128, BK = 32;
    constexpr int T = (BN == 256) ? 512 : 256;
    constexpr int NWN = BN / 32;                // warps along N
    constexpr int ABYTES = BM * BK * 4;         // 16 KB / stage
    constexpr int BBYTES = BN * BK * 4;

    extern __shared__ char smem[];
    const uint32_t smA = (uint32_t)__cvta_generic_to_shared(smem);
    const uint32_t smB = smA + STAGES * ABYTES;

    const int t = threadIdx.x, lane = t & 31, warp = t >> 5;
    const int wm = warp / NWN, wn = warp % NWN;
    const int m0 = blockIdx.y * BM, n0 = blockIdx.x * BN;
    int k0 = 0;
    if (EPI == 0) { k0 = blockIdx.z * kcnt; out += (size_t)blockIdx.z * M * N; }

    // per-thread ldmatrix address components
    const int idx = lane & 7, g = lane >> 3;
    const uint32_t xorv = (uint32_t)idx * 16u;
    uint32_t aoff[4], boff[2], acx[4], bcx[4];
    #pragma unroll
    for (int mt = 0; mt < 4; mt++)
        aoff[mt] = (uint32_t)((wm * 64 + mt * 16 + (g & 1) * 8 + idx) * 128);
    #pragma unroll
    for (int p = 0; p < 2; p++)
        boff[p] = (uint32_t)((wn * 32 + (p * 2 + (g >> 1)) * 8 + idx) * 128);
    #pragma unroll
    for (int ks = 0; ks < 4; ks++) {
        acx[ks] = ((uint32_t)(ks * 32) | (uint32_t)((g >> 1) * 16)) ^ xorv;
        bcx[ks] = ((uint32_t)(ks * 32) | (uint32_t)((g & 1) * 16)) ^ xorv;
    }

    float acc[4][4][4];
    #pragma unroll
    for (int i = 0; i < 4; i++)
        #pragma unroll
        for (int j = 0; j < 4; j++)
            #pragma unroll
            for (int q = 0; q < 4; q++) acc[i][j][q] = 0.f;

    auto load_tile = [&](int stage, int kt) {
        const int kk = k0 + kt * BK;
        #pragma unroll
        for (int f = t; f < BM * 8; f += T) {
            const int r = f >> 3, c = f & 7;
            cp16(smA + (uint32_t)stage * ABYTES + SW128((uint32_t)(r * 128 + c * 16)),
                 A + (size_t)(m0 + r) * K + kk + c * 4);
        }
        #pragma unroll
        for (int f = t; f < BN * 8; f += T) {
            const int r = f >> 3, c = f & 7;
            cp16(smB + (uint32_t)stage * BBYTES + SW128((uint32_t)(r * 128 + c * 16)),
                 Bm + (size_t)(n0 + r) * K + kk + c * 4);
        }
        asm volatile("cp.async.commit_group;" ::: "memory");
    };

    const int KT = kcnt / BK;
    #pragma unroll
    for (int s = 0; s < STAGES - 1; s++) load_tile(s, s);

    #pragma unroll 1
    for (int kt = 0; kt < KT; kt++) {
        const int st = kt % STAGES;
        asm volatile("cp.async.wait_group %0;" :: "n"(STAGES - 2));
        __syncthreads();
        if (kt + STAGES - 1 < KT)
            load_tile((kt + STAGES - 1) % STAGES, kt + STAGES - 1);
        else
            asm volatile("cp.async.commit_group;" ::: "memory");

        const uint32_t aB = smA + (uint32_t)st * ABYTES;
        const uint32_t bB = smB + (uint32_t)st * BBYTES;
        #pragma unroll
        for (int ks = 0; ks < 4; ks++) {
            uint32_t a[4][4], b[4][2];
            #pragma unroll
            for (int mt = 0; mt < 4; mt++)
                LDSM4(a[mt][0], a[mt][1], a[mt][2], a[mt][3],
                      aB + aoff[mt] + acx[ks]);
            #pragma unroll
            for (int p = 0; p < 2; p++)
                LDSM4(b[2 * p][0], b[2 * p][1], b[2 * p + 1][0], b[2 * p + 1][1],
                      bB + boff[p] + bcx[ks]);
            #pragma unroll
            for (int mt = 0; mt < 4; mt++)
                #pragma unroll
                for (int nt = 0; nt < 4; nt++)
                    MMA8(acc[mt][nt], a[mt], b[nt]);
        }
    }

    // epilogue
    #pragma unroll
    for (int mt = 0; mt < 4; mt++) {
        const int r = m0 + wm * 64 + mt * 16 + (lane >> 2);
        float pv0 = 0.f, pv1 = 0.f;
        if (EPI == 1) { pv0 = pe[r]; pv1 = pe[r + 8]; }
        #pragma unroll
        for (int nt = 0; nt < 4; nt++) {
            const int c = n0 + wn * 32 + nt * 8 + 2 * (lane & 3);
            *(float2*)(out + (size_t)r * N + c) =
                make_float2(acc[mt][nt][0], acc[mt][nt][1]);
            *(float2*)(out + (size_t)(r + 8) * N + c) =
                make_float2(acc[mt][nt][2], acc[mt][nt][3]);
            if (EPI == 1) {
                *(float2*)(out + off2 + (size_t)r * N + c) = make_float2(pv0, pv0);
                *(float2*)(out + off2 + (size_t)(r + 8) * N + c) = make_float2(pv1, pv1);
            }
        }
    }
}

// ---------------- launch ----------------
extern "C" void kernel_launch(void* const* d_in, const int* in_sizes, int n_in,
                              void* d_out, int out_size)
{
    const float* vf    = (const float*)d_in[0];
    const float* pwfs  = (const float*)d_in[1];
    const float* nwfs  = (const float*)d_in[2];
    const float* gamma = (const float*)d_in[3];
    const float* beta  = (const float*)d_in[4];
    const float* W     = (const float*)d_in[5];
    const float* bias  = (const float*)d_in[6];
    float* out = (float*)d_out;

    float *vfn_p, *emb_p, *nwn_p, *pe_p, *wr_p, *part_p;
    cudaGetSymbolAddress((void**)&vfn_p,  g_vfn);
    cudaGetSymbolAddress((void**)&emb_p,  g_emb);
    cudaGetSymbolAddress((void**)&nwn_p,  g_nwn);
    cudaGetSymbolAddress((void**)&pe_p,   g_pe);
    cudaGetSymbolAddress((void**)&wr_p,   g_wr);
    cudaGetSymbolAddress((void**)&part_p, g_part);

    // 1: merged W-round + BN partial stats
    k_prep<<<2048 + 512, 256>>>((const float4*)W, (float4*)wr_p, vf);
    // 2: BN finalize
    k_stats_final<<<D_ / 256, 256>>>(gamma, beta);
    // 3: BN apply (rounded) + p_e
    k_bn_pe<<<B_, 256>>>(vf, pwfs);
    // 4: normalize + round n_wfs
    k_rownorm<<<NN_, 128>>>((const float4*)nwfs, (float4*)nwn_p);

    // 5: GEMM1 split-K=4 partials: part[z] = vfn @ Wr^T (K chunk 1024)
    constexpr int SM1 = 3 * (128 + 128) * 32 * 4;     // 96 KB
    cudaFuncSetAttribute(k_mma<128, 0, 3>, cudaFuncAttributeMaxDynamicSharedMemorySize, SM1);
    k_mma<128, 0, 3><<<dim3(E_ / 128, B_ / 128, 4), 256, SM1>>>(
        vfn_p, wr_p, part_p, nullptr, B_, E_, D_, D_ / 4, 0);

    // 6: reduce partials + bias + relu + rownorm + round -> emb
    k_fuse_emb<<<B_, 128>>>(bias);

    // 7: GEMM2 n_e = embn @ nwn^T + fused p_e broadcast
    constexpr int SM2 = 4 * (128 + 256) * 32 * 4;     // 192 KB
    cudaFuncSetAttribute(k_mma<256, 1, 4>, cudaFuncAttributeMaxDynamicSharedMemorySize, SM2);
    const size_t off2 = (size_t)out_size / 2;
    k_mma<256, 1, 4><<<dim3(NN_ / 256, B_ / 128), 512, SM2>>>(
        emb_p, nwn_p, out, pe_p, B_, NN_, E_, E_, off2);
}

// round 5
// speedup vs baseline: 1.6537x; 1.0853x over previous
#include <cuda_runtime.h>
#include <cstdint>

#define B_   2048
#define D_   4096
#define E_   512
#define NN_  8192
#define BN_EPS  1e-5f
#define COS_EPSF 1e-8f

// ---------------- scratch (__device__ globals; no allocations allowed) ----------------
__device__ float g_psum[32][D_];
__device__ float g_psq [32][D_];
__device__ float g_scale[D_];
__device__ float g_shift[D_];
__device__ float g_vfn[B_ * D_];        // 33.5 MB (tf32-rounded)
__device__ float g_pe [B_];
__device__ float g_emb[B_ * E_];        // 4 MB (normalized, tf32-rounded)
__device__ float g_nwn[NN_ * E_];       // 16 MB (normalized, tf32-rounded)
__device__ float g_wr [E_ * D_];        // 8 MB (tf32-rounded W)
__device__ float g_part[4][B_ * E_];    // 16 MB split-K partials

// ---------------- helpers ----------------
__device__ __forceinline__ float tf32r(float x) {
    uint32_t u; asm("cvt.rna.tf32.f32 %0, %1;" : "=r"(u) : "f"(x));
    return __uint_as_float(u);
}
__device__ __forceinline__ void cp16(uint32_t dst, const void* src) {
    asm volatile("cp.async.cg.shared.global [%0], [%1], 16;" :: "r"(dst), "l"(src));
}
#define SW128(o) ((o) ^ (((o) >> 3) & 0x70))

#define LDSM4(r0, r1, r2, r3, a) \
    asm volatile("ldmatrix.sync.aligned.m8n8.x4.shared.b16 {%0,%1,%2,%3}, [%4];" \
                 : "=r"(r0), "=r"(r1), "=r"(r2), "=r"(r3) : "r"(a))

#define MMA8(d, av, bv) \
    asm volatile("mma.sync.aligned.m16n8k8.row.col.f32.tf32.tf32.f32 " \
                 "{%0,%1,%2,%3}, {%4,%5,%6,%7}, {%8,%9}, {%0,%1,%2,%3};" \
                 : "+f"((d)[0]), "+f"((d)[1]), "+f"((d)[2]), "+f"((d)[3]) \
                 : "r"((av)[0]), "r"((av)[1]), "r"((av)[2]), "r"((av)[3]), \
                   "r"((bv)[0]), "r"((bv)[1]))

// ------- merged: W tf32-round | BN partial stats | n_wfs rownorm+round ---------------
// blocks [0,2048): W round; [2048,2560): stats; [2560,6656): nwn (2 rows/block)
__global__ void __launch_bounds__(256) k_prep(const float4* __restrict__ W,
                                              float4* __restrict__ Wr,
                                              const float* __restrict__ vf,
                                              const float4* __restrict__ nwfs,
                                              float4* __restrict__ nwn) {
    const int t = threadIdx.x;
    if (blockIdx.x < 2048) {
        const int i = blockIdx.x * 256 + t;      // E*D/4 = 524288 = 2048*256 exactly
        float4 v = W[i];
        v.x = tf32r(v.x); v.y = tf32r(v.y); v.z = tf32r(v.z); v.w = tf32r(v.w);
        Wr[i] = v;
    } else if (blockIdx.x < 2560) {
        const int bid = blockIdx.x - 2048;       // 0..511
        const int c = (bid & 15) * 256 + t;
        const int chunk = bid >> 4;              // 0..31
        const int r0 = chunk * 64;
        float s = 0.f, q = 0.f;
        #pragma unroll 4
        for (int r = 0; r < 64; r++) {
            float v = vf[(size_t)(r0 + r) * D_ + c];
            s += v; q += v * v;
        }
        g_psum[chunk][c] = s;
        g_psq [chunk][c] = q;
    } else {
        const int seg = blockIdx.x - 2560;       // 0..4095, 2 rows each
        const int half = t >> 7;                 // 0/1 -> row within block
        const int tt = t & 127;
        const int row = seg * 2 + half;
        float4 v = nwfs[(size_t)row * 128 + tt];
        float s = v.x * v.x + v.y * v.y + v.z * v.z + v.w * v.w;
        #pragma unroll
        for (int o = 16; o; o >>= 1) s += __shfl_down_sync(0xffffffffu, s, o);
        __shared__ float ss[8];
        const int w = t >> 5;
        if ((t & 31) == 0) ss[w] = s;
        __syncthreads();
        const int b0 = half * 4;
        const float tot = ss[b0] + ss[b0 + 1] + ss[b0 + 2] + ss[b0 + 3];
        const float inv = 1.0f / fmaxf(sqrtf(tot), COS_EPSF);
        v.x = tf32r(v.x * inv); v.y = tf32r(v.y * inv);
        v.z = tf32r(v.z * inv); v.w = tf32r(v.w * inv);
        nwn[(size_t)row * 128 + tt] = v;
    }
}

__global__ void k_stats_final(const float* __restrict__ gamma,
                              const float* __restrict__ beta) {
    const int c = blockIdx.x * 256 + threadIdx.x;
    float s = 0.f, q = 0.f;
    #pragma unroll
    for (int i = 0; i < 32; i++) { s += g_psum[i][c]; q += g_psq[i][c]; }
    const float mean = s * (1.0f / B_);
    const float var  = q * (1.0f / B_) - mean * mean;
    const float sc   = gamma[c] * rsqrtf(var + BN_EPS);
    g_scale[c] = sc;
    g_shift[c] = beta[c] - mean * sc;
}

// ---------------- fused BN apply + p_e (row cosine); stores tf32-rounded vfn ---------
__global__ void __launch_bounds__(256) k_bn_pe(const float* __restrict__ vf,
                                               const float* __restrict__ p) {
    const int row = blockIdx.x;
    const int t = threadIdx.x;
    const float4* v4  = (const float4*)(vf + (size_t)row * D_);
    const float4* p4  = (const float4*)(p  + (size_t)row * D_);
    const float4* sc4 = (const float4*)g_scale;
    const float4* sh4 = (const float4*)g_shift;
    float4* o4 = (float4*)(g_vfn + (size_t)row * D_);

    float dot = 0.f, nv = 0.f, np = 0.f;
    #pragma unroll
    for (int u = 0; u < 2; u++) {
        const int i0 = t + u * 512;
        const float4 va = __ldcs(&v4[i0]);
        const float4 vb = __ldcs(&v4[i0 + 256]);
        const float4 pa = __ldcs(&p4[i0]);
        const float4 pb = __ldcs(&p4[i0 + 256]);
        const float4 sa = sc4[i0], sb = sc4[i0 + 256];
        const float4 ha = sh4[i0], hb = sh4[i0 + 256];
        float4 xa, xb;
        xa.x = va.x * sa.x + ha.x; xa.y = va.y * sa.y + ha.y;
        xa.z = va.z * sa.z + ha.z; xa.w = va.w * sa.w + ha.w;
        xb.x = vb.x * sb.x + hb.x; xb.y = vb.y * sb.y + hb.y;
        xb.z = vb.z * sb.z + hb.z; xb.w = vb.w * sb.w + hb.w;
        float4 ra, rb;
        ra.x = tf32r(xa.x); ra.y = tf32r(xa.y); ra.z = tf32r(xa.z); ra.w = tf32r(xa.w);
        rb.x = tf32r(xb.x); rb.y = tf32r(xb.y); rb.z = tf32r(xb.z); rb.w = tf32r(xb.w);
        o4[i0] = ra;
        o4[i0 + 256] = rb;
        dot += xa.x * pa.x + xa.y * pa.y + xa.z * pa.z + xa.w * pa.w;
        dot += xb.x * pb.x + xb.y * pb.y + xb.z * pb.z + xb.w * pb.w;
        nv  += xa.x * xa.x + xa.y * xa.y + xa.z * xa.z + xa.w * xa.w;
        nv  += xb.x * xb.x + xb.y * xb.y + xb.z * xb.z + xb.w * xb.w;
        np  += pa.x * pa.x + pa.y * pa.y + pa.z * pa.z + pa.w * pa.w;
        np  += pb.x * pb.x + pb.y * pb.y + pb.z * pb.z + pb.w * pb.w;
    }
    #pragma unroll
    for (int o = 16; o; o >>= 1) {
        dot += __shfl_down_sync(0xffffffffu, dot, o);
        nv  += __shfl_down_sync(0xffffffffu, nv,  o);
        np  += __shfl_down_sync(0xffffffffu, np,  o);
    }
    __shared__ float sd[8], sn[8], sp[8];
    const int lane = t & 31, w = t >> 5;
    if (lane == 0) { sd[w] = dot; sn[w] = nv; sp[w] = np; }
    __syncthreads();
    if (t == 0) {
        float Dv = 0.f, NV = 0.f, NP = 0.f;
        #pragma unroll
        for (int i = 0; i < 8; i++) { Dv += sd[i]; NV += sn[i]; NP += sp[i]; }
        g_pe[row] = Dv / (fmaxf(sqrtf(NV), COS_EPSF) * fmaxf(sqrtf(NP), COS_EPSF));
    }
}

// ---------------- split-K reduce + bias + relu + rownorm + round -> g_emb -----------
__global__ void k_fuse_emb(const float* __restrict__ bias) {
    const int row = blockIdx.x;     // 2048
    const int t = threadIdx.x;      // 128
    float4 s = make_float4(0.f, 0.f, 0.f, 0.f);
    #pragma unroll
    for (int p = 0; p < 4; p++) {
        const float4 v = *(const float4*)(&g_part[p][(size_t)row * E_ + t * 4]);
        s.x += v.x; s.y += v.y; s.z += v.z; s.w += v.w;
    }
    const float4 bq = ((const float4*)bias)[t];
    s.x = fmaxf(s.x + bq.x, 0.f);
    s.y = fmaxf(s.y + bq.y, 0.f);
    s.z = fmaxf(s.z + bq.z, 0.f);
    s.w = fmaxf(s.w + bq.w, 0.f);
    float nrm = s.x * s.x + s.y * s.y + s.z * s.z + s.w * s.w;
    #pragma unroll
    for (int o = 16; o; o >>= 1) nrm += __shfl_down_sync(0xffffffffu, nrm, o);
    __shared__ float ss[4];
    if ((t & 31) == 0) ss[t >> 5] = nrm;
    __syncthreads();
    const float tot = ss[0] + ss[1] + ss[2] + ss[3];
    const float inv = 1.0f / fmaxf(sqrtf(tot), COS_EPSF);
    float4 o;
    o.x = tf32r(s.x * inv); o.y = tf32r(s.y * inv);
    o.z = tf32r(s.z * inv); o.w = tf32r(s.w * inv);
    *(float4*)(&g_emb[(size_t)row * E_ + t * 4]) = o;
}

// ---------------- tf32 mma.sync GEMM  C[M,N] = A[M,K_chunk] @ B[N,K_chunk]^T --------
// 128x128 tile, 256 thr, 3-stage cp.async, occupancy 2.
// EPI 0: split-K partial store (out += z*M*N, k0 = z*kcnt)
// EPI 1: out[r*N+c] = C; out[off2 + r*N+c] = pe[r]
template<int EPI>
__global__ void __launch_bounds__(256, 2)
k_mma(const float* __restrict__ A, const float* __restrict__ Bm,
      float* __restrict__ out, const float* __restrict__ pe,
      int M, int N, int K, int kcnt, size_t off2)
{
    constexpr int BM = 128, BN = 128, BK = 32, STAGES = 3, T = 256;
    constexpr int NWN = BN / 32;                // 4 warps along N
    constexpr int ABYTES = BM * BK * 4;         // 16 KB / stage
    constexpr int BBYTES = BN * BK * 4;

    extern __shared__ char smem[];
    const uint32_t smA = (uint32_t)__cvta_generic_to_shared(smem);
    const uint32_t smB = smA + STAGES * ABYTES;

    const int t = threadIdx.x, lane = t & 31, warp = t >> 5;
    const int wm = warp / NWN, wn = warp % NWN;
    const int m0 = blockIdx.y * BM, n0 = blockIdx.x * BN;
    int k0 = 0;
    if (EPI == 0) { k0 = blockIdx.z * kcnt; out += (size_t)blockIdx.z * M * N; }

    // per-thread ldmatrix address components
    const int idx = lane & 7, g = lane >> 3;
    const uint32_t xorv = (uint32_t)idx * 16u;
    uint32_t aoff[4], boff[2], acx[4], bcx[4];
    #pragma unroll
    for (int mt = 0; mt < 4; mt++)
        aoff[mt] = (uint32_t)((wm * 64 + mt * 16 + (g & 1) * 8 + idx) * 128);
    #pragma unroll
    for (int p = 0; p < 2; p++)
        boff[p] = (uint32_t)((wn * 32 + (p * 2 + (g >> 1)) * 8 + idx) * 128);
    #pragma unroll
    for (int ks = 0; ks < 4; ks++) {
        acx[ks] = ((uint32_t)(ks * 32) | (uint32_t)((g >> 1) * 16)) ^ xorv;
        bcx[ks] = ((uint32_t)(ks * 32) | (uint32_t)((g & 1) * 16)) ^ xorv;
    }

    float acc[4][4][4];
    #pragma unroll
    for (int i = 0; i < 4; i++)
        #pragma unroll
        for (int j = 0; j < 4; j++)
            #pragma unroll
            for (int q = 0; q < 4; q++) acc[i][j][q] = 0.f;

    auto load_tile = [&](int stage, int kt) {
        const int kk = k0 + kt * BK;
        #pragma unroll
        for (int f = t; f < BM * 8; f += T) {
            const int r = f >> 3, c = f & 7;
            cp16(smA + (uint32_t)stage * ABYTES + SW128((uint32_t)(r * 128 + c * 16)),
                 A + (size_t)(m0 + r) * K + kk + c * 4);
        }
        #pragma unroll
        for (int f = t; f < BN * 8; f += T) {
            const int r = f >> 3, c = f & 7;
            cp16(smB + (uint32_t)stage * BBYTES + SW128((uint32_t)(r * 128 + c * 16)),
                 Bm + (size_t)(n0 + r) * K + kk + c * 4);
        }
        asm volatile("cp.async.commit_group;" ::: "memory");
    };

    const int KT = kcnt / BK;
    #pragma unroll
    for (int s = 0; s < STAGES - 1; s++) load_tile(s, s);

    #pragma unroll 1
    for (int kt = 0; kt < KT; kt++) {
        const int st = kt % STAGES;
        asm volatile("cp.async.wait_group %0;" :: "n"(STAGES - 2));
        __syncthreads();
        if (kt + STAGES - 1 < KT)
            load_tile((kt + STAGES - 1) % STAGES, kt + STAGES - 1);
        else
            asm volatile("cp.async.commit_group;" ::: "memory");

        const uint32_t aB = smA + (uint32_t)st * ABYTES;
        const uint32_t bB = smB + (uint32_t)st * BBYTES;
        #pragma unroll
        for (int ks = 0; ks < 4; ks++) {
            uint32_t a[4][4], b[4][2];
            #pragma unroll
            for (int mt = 0; mt < 4; mt++)
                LDSM4(a[mt][0], a[mt][1], a[mt][2], a[mt][3],
                      aB + aoff[mt] + acx[ks]);
            #pragma unroll
            for (int p = 0; p < 2; p++)
                LDSM4(b[2 * p][0], b[2 * p][1], b[2 * p + 1][0], b[2 * p + 1][1],
                      bB + boff[p] + bcx[ks]);
            #pragma unroll
            for (int mt = 0; mt < 4; mt++)
                #pragma unroll
                for (int nt = 0; nt < 4; nt++)
                    MMA8(acc[mt][nt], a[mt], b[nt]);
        }
    }

    // epilogue
    #pragma unroll
    for (int mt = 0; mt < 4; mt++) {
        const int r = m0 + wm * 64 + mt * 16 + (lane >> 2);
        float pv0 = 0.f, pv1 = 0.f;
        if (EPI == 1) { pv0 = pe[r]; pv1 = pe[r + 8]; }
        #pragma unroll
        for (int nt = 0; nt < 4; nt++) {
            const int c = n0 + wn * 32 + nt * 8 + 2 * (lane & 3);
            *(float2*)(out + (size_t)r * N + c) =
                make_float2(acc[mt][nt][0], acc[mt][nt][1]);
            *(float2*)(out + (size_t)(r + 8) * N + c) =
                make_float2(acc[mt][nt][2], acc[mt][nt][3]);
            if (EPI == 1) {
                *(float2*)(out + off2 + (size_t)r * N + c) = make_float2(pv0, pv0);
                *(float2*)(out + off2 + (size_t)(r + 8) * N + c) = make_float2(pv1, pv1);
            }
        }
    }
}

// ---------------- launch ----------------
extern "C" void kernel_launch(void* const* d_in, const int* in_sizes, int n_in,
                              void* d_out, int out_size)
{
    const float* vf    = (const float*)d_in[0];
    const float* pwfs  = (const float*)d_in[1];
    const float* nwfs  = (const float*)d_in[2];
    const float* gamma = (const float*)d_in[3];
    const float* beta  = (const float*)d_in[4];
    const float* W     = (const float*)d_in[5];
    const float* bias  = (const float*)d_in[6];
    float* out = (float*)d_out;

    float *vfn_p, *emb_p, *nwn_p, *pe_p, *wr_p, *part_p;
    cudaGetSymbolAddress((void**)&vfn_p,  g_vfn);
    cudaGetSymbolAddress((void**)&emb_p,  g_emb);
    cudaGetSymbolAddress((void**)&nwn_p,  g_nwn);
    cudaGetSymbolAddress((void**)&pe_p,   g_pe);
    cudaGetSymbolAddress((void**)&wr_p,   g_wr);
    cudaGetSymbolAddress((void**)&part_p, g_part);

    // 1: merged W-round + BN partial stats + n_wfs rownorm
    k_prep<<<2048 + 512 + 4096, 256>>>((const float4*)W, (float4*)wr_p, vf,
                                       (const float4*)nwfs, (float4*)nwn_p);
    // 2: BN finalize
    k_stats_final<<<D_ / 256, 256>>>(gamma, beta);
    // 3: BN apply (rounded) + p_e
    k_bn_pe<<<B_, 256>>>(vf, pwfs);

    // 4: GEMM1 split-K=4 partials: part[z] = vfn @ Wr^T (K chunk 1024)
    constexpr int SM1 = 3 * (128 + 128) * 32 * 4;     // 96 KB
    cudaFuncSetAttribute(k_mma<0>, cudaFuncAttributeMaxDynamicSharedMemorySize, SM1);
    k_mma<0><<<dim3(E_ / 128, B_ / 128, 4), 256, SM1>>>(
        vfn_p, wr_p, part_p, nullptr, B_, E_, D_, D_ / 4, 0);

    // 5: reduce partials + bias + relu + rownorm + round -> emb
    k_fuse_emb<<<B_, 128>>>(bias);

    // 6: GEMM2 n_e = embn @ nwn^T + fused p_e broadcast (occ-2 config)
    cudaFuncSetAttribute(k_mma<1>, cudaFuncAttributeMaxDynamicSharedMemorySize, SM1);
    const size_t off2 = (size_t)out_size / 2;
    k_mma<1><<<dim3(NN_ / 128, B_ / 128), 256, SM1>>>(
        emb_p, nwn_p, out, pe_p, B_, NN_, E_, E_, off2);
}